// round 15
// baseline (speedup 1.0000x reference)
#include <cuda_runtime.h>

// 2-layer GRU (PyTorch semantics) + linear head. T=512, B=4096, I=2, H=64.
// 148 persistent blocks x 512 threads (all SMs), 28 batch rows/block (padded
// 4144; x clamped, out predicated). 2 independent 256-thread groups of 14
// rows. Warps 0-3 of a group: 8-row region; 4-7: 6-row region.
// R14 = R13 + phase reorder to fill barrier waits with FMA work:
//   G0 -> E0 -> G1B(recurrent, h1(t-1)) -> bar -> G1A(input, h0(t)) -> E1 -> bar
// G1B depends only on data sealed at the previous end-of-step bar, so the
// inter-warp E0 straggler wait is overlapped by ~770 cyc of same-warp GEMM.
// Per-thread: 1 j x NB rows, in-warp k-split (lane bit 4), f32x2 (even,odd)-k
// packing; all partial sums exchange-added via shfl.bfly(16) at the gates.

#define TT   512
#define BB   4096
#define NBLK 148
#define NTHR 512

typedef unsigned long long u64;

// SMEM (floats):
//  w0 [32 kp][384]: per kp: RZ (64 j x {R u64, Z u64}) + N (64 j x u64) @+256
//  w1 [64 kp][384]: kp<32 = Wih1, kp>=32 = Whh1
//  h  @36864, per group 3584: hp0 2 bufs x 896, hp1 2 bufs x 896
//     row layout per kp: 28 floats = [bg0: 8 rows x2][bg1: 6 rows x2]
#define OFF_W0 0
#define OFF_W1 12288
#define OFF_H  36864
#define GRPH   3584
#define SMEM_FLOATS (OFF_H + 2*GRPH)     // 44032
#define SMEM_BYTES  (SMEM_FLOATS * 4)    // 176128

__device__ __forceinline__ void ffma2(u64& d, u64 a, u64 b) {
    asm("fma.rn.f32x2 %0, %1, %2, %0;" : "+l"(d) : "l"(a), "l"(b));
}
__device__ __forceinline__ void fadd2(u64& d, u64 a) {
    asm("add.rn.f32x2 %0, %0, %1;" : "+l"(d) : "l"(a));
}
__device__ __forceinline__ float fold(u64 v) {
    float lo, hi;
    asm("mov.b64 {%0,%1}, %2;" : "=f"(lo), "=f"(hi) : "l"(v));
    return lo + hi;
}
__device__ __forceinline__ float tanh_(float x) {
    float r; asm("tanh.approx.f32 %0, %1;" : "=f"(r) : "f"(x)); return r;
}
__device__ __forceinline__ float sigm(float x) {
    return fmaf(tanh_(0.5f * x), 0.5f, 0.5f);
}

#define GRPBAR256(id) asm volatile("bar.sync %0, 256;" :: "r"(id) : "memory")

// GEMM over NKP k-pairs, NB rows. wrz = base + j*4 (stride 384), wn = +256+j*2.
// hb = h base (stride 28 floats/kp) + region offset. Fully unrolled.
template<int NKP, int NB>
__device__ __forceinline__ void gemm_rzn(const float* __restrict__ wrz,
                                         const float* __restrict__ wn,
                                         const float* __restrict__ hb,
                                         u64 aR[NB], u64 aZ[NB], u64 aN[NB])
{
    #pragma unroll
    for (int kp = 0; kp < NKP; ++kp) {
        ulonglong2 wv = *(const ulonglong2*)(wrz + kp * 384);
        u64 wNv = *(const u64*)(wn + kp * 384);
        const float* hr = hb + kp * 28;
        u64 hv[NB];
        {
            ulonglong2 t0 = *(const ulonglong2*)(hr);
            ulonglong2 t1 = *(const ulonglong2*)(hr + 4);
            hv[0] = t0.x; hv[1] = t0.y; hv[2] = t1.x; hv[3] = t1.y;
            if constexpr (NB == 8) {
                ulonglong2 t2 = *(const ulonglong2*)(hr + 8);
                ulonglong2 t3 = *(const ulonglong2*)(hr + 12);
                hv[4] = t2.x; hv[5] = t2.y; hv[6] = t3.x; hv[7] = t3.y;
            } else {
                ulonglong2 t2 = *(const ulonglong2*)(hr + 8);
                hv[4] = t2.x; hv[5] = t2.y;
            }
        }
        #pragma unroll
        for (int b = 0; b < NB; ++b) {
            ffma2(aR[b], hv[b], wv.x);
            ffma2(aZ[b], hv[b], wv.y);
            ffma2(aN[b], hv[b], wNv);
        }
    }
}

struct Ctx {
    const float* xrow[4];              // t-invariant clamped x row pointers
    float* hp0; float* hp1;
    const float* w0rz;  const float* w0n;
    const float* w1Arz; const float* w1An;   // input side (Wih1), my k-half
    const float* w1Brz; const float* w1Bn;   // recurrent (Whh1), my k-half
    int ks, bgf, st0, bar_id;
    float wxr0, wxr1, wxz0, wxz1, wxn0, wxn1;
    float br0, bz0, bnx0, bnh0, br1, bz1, bnx1, bnh1;
};

template<int NB>
__device__ __forceinline__ void time_loop(const Ctx c, float* hprev0, float* hprev1)
{
    constexpr int F = NB / 2;
    const int ks = c.ks;
    for (int t = 0; t < TT; ++t) {
        const int cur = t & 1, nxt = cur ^ 1;
        float* hp0c = c.hp0 + cur * 896;
        float* hp0n = c.hp0 + nxt * 896;
        float* hp1c = c.hp1 + cur * 896;
        float* hp1n = c.hp1 + nxt * 896;

        // x(t) for my F finalized rows (pointers pre-clamped, t-invariant rows)
        const size_t toff = (size_t)t * (BB * 2);
        float xf[2 * F];
        #pragma unroll
        for (int i = 0; i < F; ++i) {
            float2 v = *(const float2*)(c.xrow[i] + toff);
            xf[2 * i] = v.x; xf[2 * i + 1] = v.y;
        }

        // ======== G0: layer-0 GEMM, my k-half over h0(t-1) ========
        u64 aR[NB], aZ[NB], aN[NB];
        #pragma unroll
        for (int b = 0; b < NB; ++b) { aR[b] = 0; aZ[b] = 0; aN[b] = 0; }
        gemm_rzn<16, NB>(c.w0rz, c.w0n, hp0c + ks * 448 + c.bgf, aR, aZ, aN);

        // ======== E0: k-split reduce + gates; write h0(t) -> hp0[nxt] ========
        #pragma unroll
        for (int i = 0; i < F; ++i) {
            u64 keepR = ks ? aR[F+i] : aR[i], sndR = ks ? aR[i] : aR[F+i];
            u64 keepZ = ks ? aZ[F+i] : aZ[i], sndZ = ks ? aZ[i] : aZ[F+i];
            u64 keepN = ks ? aN[F+i] : aN[i], sndN = ks ? aN[i] : aN[F+i];
            fadd2(keepR, __shfl_xor_sync(0xffffffffu, sndR, 16));
            fadd2(keepZ, __shfl_xor_sync(0xffffffffu, sndZ, 16));
            fadd2(keepN, __shfl_xor_sync(0xffffffffu, sndN, 16));
            float sR = fold(keepR), sZ = fold(keepZ), sN = fold(keepN);
            float x0 = xf[2*i], x1 = xf[2*i+1];
            float r = sigm(sR + x0 * c.wxr0 + x1 * c.wxr1 + c.br0);
            float z = sigm(sZ + x0 * c.wxz0 + x1 * c.wxz1 + c.bz0);
            float n = tanh_(x0 * c.wxn0 + x1 * c.wxn1 + c.bnx0 + r * (sN + c.bnh0));
            float h = n + z * (hprev0[i] - n);
            hprev0[i] = h;
            hp0n[c.st0 + i * 2] = h;
        }

        // ==== G1B: layer-1 RECURRENT half (Whh1, my k-half) over h1(t-1).
        //      Depends only on data sealed at the previous end-of-step bar —
        //      this work fills the wait for other warps' E0. ====
        u64 cR[NB], cZ[NB], cN[NB];
        #pragma unroll
        for (int b = 0; b < NB; ++b) { cR[b] = 0; cZ[b] = 0; cN[b] = 0; }
        gemm_rzn<16, NB>(c.w1Brz, c.w1Bn, hp1c + ks * 448 + c.bgf, cR, cZ, cN);
        float cNhf[NB];
        #pragma unroll
        for (int b = 0; b < NB; ++b) { cNhf[b] = fold(cN[b]); cN[b] = 0; }

        GRPBAR256(c.bar_id);   // h0(t) visible within group

        // ======== G1A: layer-1 INPUT half (Wih1, my k-half) over fresh h0(t) ====
        gemm_rzn<16, NB>(c.w1Arz, c.w1An, hp0n + ks * 448 + c.bgf, cR, cZ, cN);

        // ======== E1: symmetric exchange + gates; write h1(t) -> hp1[nxt] ======
        #pragma unroll
        for (int i = 0; i < F; ++i) {
            u64 keepR = ks ? cR[F+i] : cR[i], sndR = ks ? cR[i] : cR[F+i];
            u64 keepZ = ks ? cZ[F+i] : cZ[i], sndZ = ks ? cZ[i] : cZ[F+i];
            u64 keepNx = ks ? cN[F+i] : cN[i], sndNx = ks ? cN[i] : cN[F+i];
            float keepNh = ks ? cNhf[F+i] : cNhf[i];
            float sndNh  = ks ? cNhf[i]   : cNhf[F+i];
            fadd2(keepR,  __shfl_xor_sync(0xffffffffu, sndR, 16));
            fadd2(keepZ,  __shfl_xor_sync(0xffffffffu, sndZ, 16));
            fadd2(keepNx, __shfl_xor_sync(0xffffffffu, sndNx, 16));
            float nh = keepNh + __shfl_xor_sync(0xffffffffu, sndNh, 16);
            float sR = fold(keepR), sZ = fold(keepZ), nx = fold(keepNx);
            float r = sigm(sR + c.br1);
            float z = sigm(sZ + c.bz1);
            float n = tanh_(nx + c.bnx1 + r * (nh + c.bnh1));
            float h = n + z * (hprev1[i] - n);
            hprev1[i] = h;
            hp1n[c.st0 + i * 2] = h;
        }
        GRPBAR256(c.bar_id);   // h1(t) sealed for next step's G1B
    }
}

extern "C" __global__ void __launch_bounds__(NTHR, 1)
gru2_kernel(const float* __restrict__ gx,
            const float* __restrict__ Wih0, const float* __restrict__ Whh0,
            const float* __restrict__ bih0, const float* __restrict__ bhh0,
            const float* __restrict__ Wih1, const float* __restrict__ Whh1,
            const float* __restrict__ bih1, const float* __restrict__ bhh1,
            const float* __restrict__ Wp,   const float* __restrict__ bp,
            float* __restrict__ out)
{
    extern __shared__ __align__(16) float sm[];
    const int tid = threadIdx.x;

    // ---- one-time weight staging (R6/R11 layout) ----
    for (int i = tid; i < 12288; i += NTHR) {
        int kp = i / 384, r = i % 384;
        float v;
        if (r < 256) {
            int j = r >> 2, sub = r & 3, gate = sub >> 1, e = sub & 1;
            v = Whh0[(gate * 64 + j) * 64 + 2 * kp + e];
        } else {
            int rr = r - 256, j = rr >> 1, e = rr & 1;
            v = Whh0[(128 + j) * 64 + 2 * kp + e];
        }
        sm[OFF_W0 + i] = v;
    }
    for (int i = tid; i < 24576; i += NTHR) {
        int kp = i / 384, r = i % 384;
        const float* W = (kp < 32) ? Wih1 : Whh1;
        int k0 = 2 * (kp & 31);
        float v;
        if (r < 256) {
            int j = r >> 2, sub = r & 3, gate = sub >> 1, e = sub & 1;
            v = W[(gate * 64 + j) * 64 + k0 + e];
        } else {
            int rr = r - 256, j = rr >> 1, e = rr & 1;
            v = W[(128 + j) * 64 + k0 + e];
        }
        sm[OFF_W1 + i] = v;
    }
    for (int i = tid; i < 2 * GRPH; i += NTHR) sm[OFF_H + i] = 0.0f;

    // ---- per-thread mapping ----
    const int warp   = tid >> 5;
    const int g      = tid >> 8;            // group 0/1 (warps 0-7 | 8-15)
    const int warp_g = warp & 7;
    const int jw     = warp_g & 3;          // 4 j-warps cover 64 j
    const int bg     = warp_g >> 2;         // region: 0 = 8 rows, 1 = 6 rows
    const int lane   = tid & 31;
    const int ks     = lane >> 4;
    const int jq     = lane & 15;
    const int j      = jw * 16 + jq;        // my j column (0..63)
    const int kpj    = j >> 1, ej = j & 1;
    const int F      = bg ? 3 : 4;
    const int lrow0  = bg * 8 + ks * F;     // first finalized local row (of 14)
    const int bglob  = blockIdx.x * 28 + g * 14 + lrow0;

    Ctx c;
    c.ks = ks;
    c.bgf = bg * 16;
    c.st0 = kpj * 28 + lrow0 * 2 + ej;
    c.bar_id = g + 1;

    // t-invariant clamped x row pointers
    #pragma unroll
    for (int i = 0; i < 4; ++i) {
        int br = bglob + i; if (br > BB - 1) br = BB - 1;
        c.xrow[i] = gx + (size_t)br * 2;
    }

    c.wxr0 = Wih0[j*2];        c.wxr1 = Wih0[j*2+1];
    c.wxz0 = Wih0[(64+j)*2];   c.wxz1 = Wih0[(64+j)*2+1];
    c.wxn0 = Wih0[(128+j)*2];  c.wxn1 = Wih0[(128+j)*2+1];
    c.br0 = bih0[j]    + bhh0[j];
    c.bz0 = bih0[64+j] + bhh0[64+j];
    c.bnx0 = bih0[128+j]; c.bnh0 = bhh0[128+j];
    c.br1 = bih1[j]    + bhh1[j];
    c.bz1 = bih1[64+j] + bhh1[64+j];
    c.bnx1 = bih1[128+j]; c.bnh1 = bhh1[128+j];

    c.w0rz  = sm + OFF_W0 + (ks * 16) * 384 + j * 4;
    c.w0n   = sm + OFF_W0 + (ks * 16) * 384 + 256 + j * 2;
    c.w1Arz = sm + OFF_W1 + (ks * 16) * 384 + j * 4;          // Wih1 kp ks-half
    c.w1An  = sm + OFF_W1 + (ks * 16) * 384 + 256 + j * 2;
    c.w1Brz = sm + OFF_W1 + ((32 + ks * 16)) * 384 + j * 4;   // Whh1 kp ks-half
    c.w1Bn  = sm + OFF_W1 + ((32 + ks * 16)) * 384 + 256 + j * 2;

    c.hp0 = sm + OFF_H + g * GRPH;          // 2 bufs x 896
    c.hp1 = c.hp0 + 1792;                   // 2 bufs x 896

    float hprev0[4] = {0.f, 0.f, 0.f, 0.f};
    float hprev1[4] = {0.f, 0.f, 0.f, 0.f};

    __syncthreads();

    if (bg == 0) time_loop<8>(c, hprev0, hprev1);
    else         time_loop<6>(c, hprev0, hprev1);

    // ---- projection: out[b] = sum_j Wp[j]*h0f[j] + Wp[64+j]*h1f[j] + bp ----
    __syncthreads();   // all groups done with h buffers
    {
        float* scr = sm + OFF_H;   // [28 rows][stride 68]
        const float wp0 = Wp[j], wp1 = Wp[64 + j];
        #pragma unroll
        for (int i = 0; i < 4; ++i) {
            if (i < F) {
                int lr = g * 14 + lrow0 + i;
                scr[lr * 68 + j] = wp0 * hprev0[i] + wp1 * hprev1[i];
            }
        }
        __syncthreads();
        if (tid < 28) {
            int rowg = blockIdx.x * 28 + tid;
            if (rowg < BB) {
                float s = bp[0];
                #pragma unroll 8
                for (int jj = 0; jj < 64; ++jj) s += scr[tid * 68 + jj];
                out[rowg] = s;
            }
        }
    }
}

extern "C" void kernel_launch(void* const* d_in, const int* in_sizes, int n_in,
                              void* d_out, int out_size)
{
    (void)in_sizes; (void)n_in; (void)out_size;
    const float* x    = (const float*)d_in[0];
    const float* Wih0 = (const float*)d_in[1];
    const float* Whh0 = (const float*)d_in[2];
    const float* bih0 = (const float*)d_in[3];
    const float* bhh0 = (const float*)d_in[4];
    const float* Wih1 = (const float*)d_in[5];
    const float* Whh1 = (const float*)d_in[6];
    const float* bih1 = (const float*)d_in[7];
    const float* bhh1 = (const float*)d_in[8];
    const float* Wp   = (const float*)d_in[9];
    const float* bp   = (const float*)d_in[10];
    float* out = (float*)d_out;

    cudaFuncSetAttribute(gru2_kernel, cudaFuncAttributeMaxDynamicSharedMemorySize, SMEM_BYTES);
    gru2_kernel<<<NBLK, NTHR, SMEM_BYTES>>>(x, Wih0, Whh0, bih0, bhh0,
                                            Wih1, Whh1, bih1, bhh1, Wp, bp, out);
}

// round 16
// speedup vs baseline: 1.0927x; 1.0927x over previous
#include <cuda_runtime.h>

// 2-layer GRU (PyTorch semantics) + linear head. T=512, B=4096, I=2, H=64.
// 148 persistent blocks x 512 threads (all SMs), 28 batch rows/block (padded
// 4144; x clamped, out predicated). 2 independent 256-thread groups of 14
// rows, 1 group-barrier/step (R13 structure).
// R15 = R13 with BALANCED warp regions: 7+7 rows (was 8+6) so every warp in a
// group issues exactly the same FMA work per step -> no intra-group straggler
// idling at the barrier. NB=7 tile; k-split finalize is 4 rows (ks0) / 3 rows
// (ks1) with one dummy exchange round (shfls unconditional, gates predicated).
// h row stride 32 floats with pads so both 14-float regions are 16B-aligned.

#define TT   512
#define BB   4096
#define NBLK 148
#define NTHR 512

typedef unsigned long long u64;

// SMEM (floats):
//  w0 [32 kp][384]: per kp: RZ (64 j x {R u64, Z u64}) + N (64 j x u64) @+256
//  w1 [64 kp][384]: kp<32 = Wih1, kp>=32 = Whh1
//  h  @36864, per group 4096: hp0 2 bufs x 1024, hp1 2 bufs x 1024
//     row layout per kp: 32 floats = [reg0: 7 rows x2][pad2][reg1: 7 rows x2][pad2]
#define OFF_W0 0
#define OFF_W1 12288
#define OFF_H  36864
#define GRPH   4096
#define SMEM_FLOATS (OFF_H + 2*GRPH)     // 45056
#define SMEM_BYTES  (SMEM_FLOATS * 4)    // 180224

__device__ __forceinline__ void ffma2(u64& d, u64 a, u64 b) {
    asm("fma.rn.f32x2 %0, %1, %2, %0;" : "+l"(d) : "l"(a), "l"(b));
}
__device__ __forceinline__ void fadd2(u64& d, u64 a) {
    asm("add.rn.f32x2 %0, %0, %1;" : "+l"(d) : "l"(a));
}
__device__ __forceinline__ float fold(u64 v) {
    float lo, hi;
    asm("mov.b64 {%0,%1}, %2;" : "=f"(lo), "=f"(hi) : "l"(v));
    return lo + hi;
}
__device__ __forceinline__ float tanh_(float x) {
    float r; asm("tanh.approx.f32 %0, %1;" : "=f"(r) : "f"(x)); return r;
}
__device__ __forceinline__ float sigm(float x) {
    return fmaf(tanh_(0.5f * x), 0.5f, 0.5f);
}

#define GRPBAR256(id) asm volatile("bar.sync %0, 256;" :: "r"(id) : "memory")

// GEMM over NKP k-pairs, 7 rows. wrz = base + j*4 (stride 384), wn = +256+j*2.
// hb = h base (stride 32 floats/kp) + region offset (0 or 16). Fully unrolled.
template<int NKP>
__device__ __forceinline__ void gemm_rzn7(const float* __restrict__ wrz,
                                          const float* __restrict__ wn,
                                          const float* __restrict__ hb,
                                          u64 aR[7], u64 aZ[7], u64 aN[7])
{
    #pragma unroll
    for (int kp = 0; kp < NKP; ++kp) {
        ulonglong2 wv = *(const ulonglong2*)(wrz + kp * 384);
        u64 wNv = *(const u64*)(wn + kp * 384);
        const float* hr = hb + kp * 32;
        u64 hv[7];
        {
            ulonglong2 t0 = *(const ulonglong2*)(hr);
            ulonglong2 t1 = *(const ulonglong2*)(hr + 4);
            ulonglong2 t2 = *(const ulonglong2*)(hr + 8);
            u64 t3 = *(const u64*)(hr + 12);
            hv[0] = t0.x; hv[1] = t0.y; hv[2] = t1.x; hv[3] = t1.y;
            hv[4] = t2.x; hv[5] = t2.y; hv[6] = t3;
        }
        #pragma unroll
        for (int b = 0; b < 7; ++b) {
            ffma2(aR[b], hv[b], wv.x);
            ffma2(aZ[b], hv[b], wv.y);
            ffma2(aN[b], hv[b], wNv);
        }
    }
}

struct Ctx {
    const float* xrow[4];              // t-invariant clamped x row pointers
    float* hp0; float* hp1;
    const float* w0rz; const float* w0n;
    const float* w1rz; const float* w1n;
    int ks, bgf, st0, bar_id;
    float wxr0, wxr1, wxz0, wxz1, wxn0, wxn1;
    float br0, bz0, bnx0, bnh0, br1, bz1, bnx1, bnh1;
};

__device__ __forceinline__ void time_loop(const Ctx c, float* hprev0, float* hprev1)
{
    const int ks = c.ks;
    for (int t = 0; t < TT; ++t) {
        const int cur = t & 1, nxt = cur ^ 1;
        float* hp0c = c.hp0 + cur * 1024;
        float* hp0n = c.hp0 + nxt * 1024;
        float* hp1c = c.hp1 + cur * 1024;
        float* hp1n = c.hp1 + nxt * 1024;

        // x(t) for my finalized rows (pointers pre-clamped, t-invariant rows)
        const size_t toff = (size_t)t * (BB * 2);
        float xf[8];
        #pragma unroll
        for (int i = 0; i < 4; ++i) {
            float2 v = *(const float2*)(c.xrow[i] + toff);
            xf[2 * i] = v.x; xf[2 * i + 1] = v.y;
        }

        // ======== G0: layer-0 GEMM, my k-half (16 kp) over h0(t-1) ========
        u64 aR[7], aZ[7], aN[7];
        #pragma unroll
        for (int b = 0; b < 7; ++b) { aR[b] = 0; aZ[b] = 0; aN[b] = 0; }
        gemm_rzn7<16>(c.w0rz, c.w0n, hp0c + ks * 512 + c.bgf, aR, aZ, aN);

        // ======== E0: exchange rounds + gates; write h0(t) -> hp0[nxt] ========
        // ks0 finalizes region rows 0..3, ks1 rows 4..6 (round 3 dummy for ks1).
        #pragma unroll
        for (int i = 0; i < 4; ++i) {
            const int ki = (i < 3) ? 4 + i : 6;
            const int idxk = ks ? ki : i;
            const int idxs = ks ? i : ki;
            u64 keepR = aR[idxk], sndR = aR[idxs];
            u64 keepZ = aZ[idxk], sndZ = aZ[idxs];
            u64 keepN = aN[idxk], sndN = aN[idxs];
            fadd2(keepR, __shfl_xor_sync(0xffffffffu, sndR, 16));
            fadd2(keepZ, __shfl_xor_sync(0xffffffffu, sndZ, 16));
            fadd2(keepN, __shfl_xor_sync(0xffffffffu, sndN, 16));
            if (!ks || i < 3) {
                float sR = fold(keepR), sZ = fold(keepZ), sN = fold(keepN);
                float x0 = xf[2*i], x1 = xf[2*i+1];
                float r = sigm(sR + x0 * c.wxr0 + x1 * c.wxr1 + c.br0);
                float z = sigm(sZ + x0 * c.wxz0 + x1 * c.wxz1 + c.bz0);
                float n = tanh_(x0 * c.wxn0 + x1 * c.wxn1 + c.bnx0 + r * (sN + c.bnh0));
                float h = n + z * (hprev0[i] - n);
                hprev0[i] = h;
                hp0n[c.st0 + i * 2] = h;
            }
        }
        GRPBAR256(c.bar_id);   // h0(t) visible within group (only bar this step)

        // ==== G1: layer-1 GEMM (contiguous 32 kp). ks0: input side (Wih1) over
        //      hp0[nxt] (fresh h0); ks1: recurrent (Whh1) over hp1[cur]. ====
        u64 cR[7], cZ[7], cN[7];
        #pragma unroll
        for (int b = 0; b < 7; ++b) { cR[b] = 0; cZ[b] = 0; cN[b] = 0; }
        gemm_rzn7<32>(c.w1rz, c.w1n, (ks ? hp1c : hp0n) + c.bgf, cR, cZ, cN);

        // ======== E1: exchange rounds + gates; write h1(t) -> hp1[nxt] ========
        #pragma unroll
        for (int i = 0; i < 4; ++i) {
            const int ki = (i < 3) ? 4 + i : 6;
            const int idxk = ks ? ki : i;
            const int idxs = ks ? i : ki;
            u64 keepR = cR[idxk], sndR = cR[idxs];
            u64 keepZ = cZ[idxk], sndZ = cZ[idxs];
            u64 keepN = cN[idxk], sndN = cN[idxs];
            fadd2(keepR, __shfl_xor_sync(0xffffffffu, sndR, 16));
            fadd2(keepZ, __shfl_xor_sync(0xffffffffu, sndZ, 16));
            u64 rcvN = __shfl_xor_sync(0xffffffffu, sndN, 16);
            if (!ks || i < 3) {
                float sR = fold(keepR), sZ = fold(keepZ);
                float fm = fold(keepN), fr = fold(rcvN);
                float nx = ks ? fr : fm;      // input-side partial came from ks0
                float nh = ks ? fm : fr;      // recurrent partial came from ks1
                float r = sigm(sR + c.br1);
                float z = sigm(sZ + c.bz1);
                float n = tanh_(nx + c.bnx1 + r * (nh + c.bnh1));
                float h = n + z * (hprev1[i] - n);
                hprev1[i] = h;
                hp1n[c.st0 + i * 2] = h;
            }
        }
        // no second barrier: next step's bar (after E0) orders E1 stores before
        // G1(t+1) reads hp1, and hp0[cur]'s reuse in E0(t+1) after G0(t)'s reads.
    }
}

extern "C" __global__ void __launch_bounds__(NTHR, 1)
gru2_kernel(const float* __restrict__ gx,
            const float* __restrict__ Wih0, const float* __restrict__ Whh0,
            const float* __restrict__ bih0, const float* __restrict__ bhh0,
            const float* __restrict__ Wih1, const float* __restrict__ Whh1,
            const float* __restrict__ bih1, const float* __restrict__ bhh1,
            const float* __restrict__ Wp,   const float* __restrict__ bp,
            float* __restrict__ out)
{
    extern __shared__ __align__(16) float sm[];
    const int tid = threadIdx.x;

    // ---- one-time weight staging (R6/R11 layout) ----
    for (int i = tid; i < 12288; i += NTHR) {
        int kp = i / 384, r = i % 384;
        float v;
        if (r < 256) {
            int j = r >> 2, sub = r & 3, gate = sub >> 1, e = sub & 1;
            v = Whh0[(gate * 64 + j) * 64 + 2 * kp + e];
        } else {
            int rr = r - 256, j = rr >> 1, e = rr & 1;
            v = Whh0[(128 + j) * 64 + 2 * kp + e];
        }
        sm[OFF_W0 + i] = v;
    }
    for (int i = tid; i < 24576; i += NTHR) {
        int kp = i / 384, r = i % 384;
        const float* W = (kp < 32) ? Wih1 : Whh1;
        int k0 = 2 * (kp & 31);
        float v;
        if (r < 256) {
            int j = r >> 2, sub = r & 3, gate = sub >> 1, e = sub & 1;
            v = W[(gate * 64 + j) * 64 + k0 + e];
        } else {
            int rr = r - 256, j = rr >> 1, e = rr & 1;
            v = W[(128 + j) * 64 + k0 + e];
        }
        sm[OFF_W1 + i] = v;
    }
    for (int i = tid; i < 2 * GRPH; i += NTHR) sm[OFF_H + i] = 0.0f;

    // ---- per-thread mapping ----
    const int warp   = tid >> 5;
    const int g      = tid >> 8;            // group 0/1 (warps 0-7 | 8-15)
    const int warp_g = warp & 7;
    const int jw     = warp_g & 3;          // 4 j-warps cover 64 j
    const int bg     = warp_g >> 2;         // region 0 or 1 (7 rows each)
    const int lane   = tid & 31;
    const int ks     = lane >> 4;
    const int jq     = lane & 15;
    const int j      = jw * 16 + jq;        // my j column (0..63)
    const int kpj    = j >> 1, ej = j & 1;
    const int F      = ks ? 3 : 4;          // finalized rows this lane-half
    const int lrow0  = bg * 7 + (ks ? 4 : 0);   // first finalized local row (of 14)
    const int bglob  = blockIdx.x * 28 + g * 14 + lrow0;

    Ctx c;
    c.ks = ks;
    c.bgf = bg * 16;
    c.st0 = kpj * 32 + bg * 16 + (ks ? 8 : 0) + ej;
    c.bar_id = g + 1;

    // t-invariant clamped x row pointers (4th is dummy-clamped for ks1)
    #pragma unroll
    for (int i = 0; i < 4; ++i) {
        int br = bglob + i; if (br > BB - 1) br = BB - 1;
        c.xrow[i] = gx + (size_t)br * 2;
    }

    c.wxr0 = Wih0[j*2];        c.wxr1 = Wih0[j*2+1];
    c.wxz0 = Wih0[(64+j)*2];   c.wxz1 = Wih0[(64+j)*2+1];
    c.wxn0 = Wih0[(128+j)*2];  c.wxn1 = Wih0[(128+j)*2+1];
    c.br0 = bih0[j]    + bhh0[j];
    c.bz0 = bih0[64+j] + bhh0[64+j];
    c.bnx0 = bih0[128+j]; c.bnh0 = bhh0[128+j];
    c.br1 = bih1[j]    + bhh1[j];
    c.bz1 = bih1[64+j] + bhh1[64+j];
    c.bnx1 = bih1[128+j]; c.bnh1 = bhh1[128+j];

    c.w0rz = sm + OFF_W0 + (ks * 16) * 384 + j * 4;
    c.w0n  = sm + OFF_W0 + (ks * 16) * 384 + 256 + j * 2;
    c.w1rz = sm + OFF_W1 + (ks * 32) * 384 + j * 4;   // ks0: Wih1, ks1: Whh1
    c.w1n  = sm + OFF_W1 + (ks * 32) * 384 + 256 + j * 2;

    c.hp0 = sm + OFF_H + g * GRPH;          // 2 bufs x 1024
    c.hp1 = c.hp0 + 2048;                   // 2 bufs x 1024

    float hprev0[4] = {0.f, 0.f, 0.f, 0.f};
    float hprev1[4] = {0.f, 0.f, 0.f, 0.f};

    __syncthreads();

    time_loop(c, hprev0, hprev1);

    // ---- projection: out[b] = sum_j Wp[j]*h0f[j] + Wp[64+j]*h1f[j] + bp ----
    __syncthreads();   // all groups done with h buffers
    {
        float* scr = sm + OFF_H;   // [28 rows][stride 68]
        const float wp0 = Wp[j], wp1 = Wp[64 + j];
        #pragma unroll
        for (int i = 0; i < 4; ++i) {
            if (i < F) {
                int lr = g * 14 + lrow0 + i;
                scr[lr * 68 + j] = wp0 * hprev0[i] + wp1 * hprev1[i];
            }
        }
        __syncthreads();
        if (tid < 28) {
            int rowg = blockIdx.x * 28 + tid;
            if (rowg < BB) {
                float s = bp[0];
                #pragma unroll 8
                for (int jj = 0; jj < 64; ++jj) s += scr[tid * 68 + jj];
                out[rowg] = s;
            }
        }
    }
}

extern "C" void kernel_launch(void* const* d_in, const int* in_sizes, int n_in,
                              void* d_out, int out_size)
{
    (void)in_sizes; (void)n_in; (void)out_size;
    const float* x    = (const float*)d_in[0];
    const float* Wih0 = (const float*)d_in[1];
    const float* Whh0 = (const float*)d_in[2];
    const float* bih0 = (const float*)d_in[3];
    const float* bhh0 = (const float*)d_in[4];
    const float* Wih1 = (const float*)d_in[5];
    const float* Whh1 = (const float*)d_in[6];
    const float* bih1 = (const float*)d_in[7];
    const float* bhh1 = (const float*)d_in[8];
    const float* Wp   = (const float*)d_in[9];
    const float* bp   = (const float*)d_in[10];
    float* out = (float*)d_out;

    cudaFuncSetAttribute(gru2_kernel, cudaFuncAttributeMaxDynamicSharedMemorySize, SMEM_BYTES);
    gru2_kernel<<<NBLK, NTHR, SMEM_BYTES>>>(x, Wih0, Whh0, bih0, bhh0,
                                            Wih1, Whh1, bih1, bhh1, Wp, bp, out);
}